// round 13
// baseline (speedup 1.0000x reference)
#include <cuda_runtime.h>
#include <cuda_fp8.h>
#include <stdint.h>

#define BB   512
#define TW   512
#define TCC  512
#define INP  16
#define HID  64
#define FD   8
#define SPB  4
#define NT   512
#define HPAD 68
#define GPAD 260   // gate array stride (floats)
#define U0S  112   // uf0 byte stride: K=96 (x16|h0 64|pad16) + 16 pad
#define U1S  144   // uf1 byte stride: K=128 (h0|h1) + 16 pad

__device__ __forceinline__ float tanha(float x) {
    float r; asm("tanh.approx.f32 %0, %1;" : "=f"(r) : "f"(x)); return r;
}
__device__ __forceinline__ float sigf(float x) {
    return fmaf(tanha(0.5f * x), 0.5f, 0.5f);
}
__device__ __forceinline__ uint8_t e4m3b(float f) {
    return (uint8_t)__nv_cvt_float_to_fp8(f, __NV_SATFINITE, __NV_E4M3);
}
__device__ __forceinline__ uint32_t pk4(float a, float b, float c, float d) {
    return (uint32_t)e4m3b(a) | ((uint32_t)e4m3b(b) << 8) |
           ((uint32_t)e4m3b(c) << 16) | ((uint32_t)e4m3b(d) << 24);
}
// m16n8k32 e4m3 x e4m3 -> f32
__device__ __forceinline__ void mma8(
    float* d, const uint32_t* a, uint32_t b0, uint32_t b1)
{
    asm("mma.sync.aligned.m16n8k32.row.col.f32.e4m3.e4m3.f32 "
        "{%0,%1,%2,%3},{%4,%5,%6,%7},{%8,%9},{%0,%1,%2,%3};"
        : "+f"(d[0]), "+f"(d[1]), "+f"(d[2]), "+f"(d[3])
        : "r"(a[0]), "r"(a[1]), "r"(a[2]), "r"(a[3]), "r"(b0), "r"(b1));
}
// g0 concat column: [Wih0(16) | Whh0(64) | zeros]
__device__ __forceinline__ float w0c(const float* Wih0, const float* Whh0,
                                     int row, int kk) {
    if (kk < 16) return Wih0[row * INP + kk];
    if (kk < 80) return Whh0[row * HID + kk - 16];
    return 0.f;
}
// g1 concat column: [Wih1(64) | Whh1(64)]
__device__ __forceinline__ float w1c(const float* Wih1, const float* Whh1,
                                     int row, int kk) {
    return (kk < 64) ? Wih1[row * HID + kk] : Whh1[row * HID + kk - 64];
}

__global__ __launch_bounds__(NT, 1) void lstm_ar_kernel(
    const float* __restrict__ x,     const int* __restrict__ lenx_g,
    const float* __restrict__ ctx,   const int* __restrict__ lctx_g,
    const float* __restrict__ Wih0,  const float* __restrict__ Whh0,
    const float* __restrict__ bih0,  const float* __restrict__ bhh0,
    const float* __restrict__ Wih1,  const float* __restrict__ Whh1,
    const float* __restrict__ bih1,  const float* __restrict__ bhh1,
    const float* __restrict__ Wd,    const float* __restrict__ bd,
    float* __restrict__ out)
{
    // B operands, n-major, e4m3 bytes
    __shared__ __align__(16) uint8_t uf0[8][U0S];
    __shared__ __align__(16) uint8_t uf1[8][U1S];
    __shared__ __align__(16) float g0sh[SPB][GPAD];  // layer-0 gates, step t
    __shared__ __align__(16) float g1sh[SPB][GPAD];  // layer-1 gates, step t-1
    __shared__ __align__(16) float h1sh[SPB][HPAD];  // fp32 h1 for projections
    __shared__ float wdsh[FD * 65];
    __shared__ float bdsh[FD];
    __shared__ float elem[SPB][FD];
    __shared__ int   lens[SPB];
    __shared__ int   ldec[SPB];

    const int tid = threadIdx.x;
    const int s0  = blockIdx.x * SPB;

    // ---- fill invalid output rows with -999 ----
    {
        const float4 m = make_float4(-999.f, -999.f, -999.f, -999.f);
        #pragma unroll
        for (int s = 0; s < SPB; s++) {
            int lc = lctx_g[s0 + s];
            float4* po = (float4*)(out + (size_t)(s0 + s) * TCC * FD);
            for (int i = lc * 2 + tid; i < (TCC * FD) / 4; i += NT) po[i] = m;
        }
    }

    // ---- zero B buffers (pads + samples 4..7 stay zero) ----
    {
        uint8_t* p0 = &uf0[0][0];
        for (int i = tid; i < 8 * U0S; i += NT) p0[i] = 0;
        uint8_t* p1 = &uf1[0][0];
        for (int i = tid; i < 8 * U1S; i += NT) p1[i] = 0;
    }

    // ---- mma identities: warp w owns M-tile w (gate rows 16w..16w+15) ----
    const int w    = tid >> 5, lane = tid & 31;
    const int g    = lane >> 2, q = lane & 3;
    const int rowA = 16 * w + g, rowB = rowA + 8;

    // A fragments (e4m3 weights): f0 = [Wih0|Whh0|0] K=96, f1 = [Wih1|Whh1] K=128
    uint32_t f0[3][4], f1[4][4];
    #pragma unroll
    for (int ks = 0; ks < 3; ks++) {
        int kb = ks * 32 + 4 * q;
        f0[ks][0] = pk4(w0c(Wih0, Whh0, rowA, kb),     w0c(Wih0, Whh0, rowA, kb + 1),
                        w0c(Wih0, Whh0, rowA, kb + 2), w0c(Wih0, Whh0, rowA, kb + 3));
        f0[ks][1] = pk4(w0c(Wih0, Whh0, rowB, kb),     w0c(Wih0, Whh0, rowB, kb + 1),
                        w0c(Wih0, Whh0, rowB, kb + 2), w0c(Wih0, Whh0, rowB, kb + 3));
        f0[ks][2] = pk4(w0c(Wih0, Whh0, rowA, kb + 16), w0c(Wih0, Whh0, rowA, kb + 17),
                        w0c(Wih0, Whh0, rowA, kb + 18), w0c(Wih0, Whh0, rowA, kb + 19));
        f0[ks][3] = pk4(w0c(Wih0, Whh0, rowB, kb + 16), w0c(Wih0, Whh0, rowB, kb + 17),
                        w0c(Wih0, Whh0, rowB, kb + 18), w0c(Wih0, Whh0, rowB, kb + 19));
    }
    #pragma unroll
    for (int ks = 0; ks < 4; ks++) {
        int kb = ks * 32 + 4 * q;
        f1[ks][0] = pk4(w1c(Wih1, Whh1, rowA, kb),     w1c(Wih1, Whh1, rowA, kb + 1),
                        w1c(Wih1, Whh1, rowA, kb + 2), w1c(Wih1, Whh1, rowA, kb + 3));
        f1[ks][1] = pk4(w1c(Wih1, Whh1, rowB, kb),     w1c(Wih1, Whh1, rowB, kb + 1),
                        w1c(Wih1, Whh1, rowB, kb + 2), w1c(Wih1, Whh1, rowB, kb + 3));
        f1[ks][2] = pk4(w1c(Wih1, Whh1, rowA, kb + 16), w1c(Wih1, Whh1, rowA, kb + 17),
                        w1c(Wih1, Whh1, rowA, kb + 18), w1c(Wih1, Whh1, rowA, kb + 19));
        f1[ks][3] = pk4(w1c(Wih1, Whh1, rowB, kb + 16), w1c(Wih1, Whh1, rowB, kb + 17),
                        w1c(Wih1, Whh1, rowB, kb + 18), w1c(Wih1, Whh1, rowB, kb + 19));
    }
    const float b0a = bih0[rowA] + bhh0[rowA], b0b = bih0[rowB] + bhh0[rowB];
    const float b1a = bih1[rowA] + bhh1[rowA], b1b = bih1[rowB] + bhh1[rowB];

    if (tid < SPB) { lens[tid] = lenx_g[s0 + tid]; ldec[tid] = lctx_g[s0 + tid] - 1; }
    for (int i = tid; i < FD * HID; i += NT) wdsh[(i >> 6) * 65 + (i & 63)] = Wd[i];
    if (tid < FD) bdsh[tid] = bd[tid];

    // ---- combine ownership: threads 0-255 layer0, 256-511 layer1 ----
    const int lay = tid >> 8;
    const int cu  = tid & 255;
    const int cs  = cu >> 6, cj = cu & 63;
    if (lay == 1) h1sh[cs][cj] = 0.f;
    float cst = 0.f;   // c0 (lay0) or c1 (lay1) for unit (cs, cj)

    __syncthreads();

    const int Tenc = max(max(lens[0], lens[1]), max(lens[2], lens[3]));
    const int Tdec = max(max(ldec[0], ldec[1]), max(ldec[2], ldec[3]));
    const int myLe = lens[cs];
    const int myLd = ldec[cs];

    const int ps = tid >> 4, pk = tid & 15;  // x prefetch (tid < 64)
    const int ds = tid >> 3, dk = tid & 7;   // ctx prefetch / projection (tid < 32)

    // ---- encoder prologue: x(0) -> uf0; g0(0) via mma (h0 = 0) ----
    if (tid < 64) uf0[ps][pk] = e4m3b(x[((size_t)(s0 + ps) * TW) * INP + pk]);
    __syncthreads();
    {
        float d[4] = {b0a, b0a, b0b, b0b};
        #pragma unroll
        for (int ks = 0; ks < 3; ks++) {
            uint32_t bv0 = *(const uint32_t*)&uf0[g][ks * 32 + 4 * q];
            uint32_t bv1 = *(const uint32_t*)&uf0[g][ks * 32 + 16 + 4 * q];
            mma8(d, f0[ks], bv0, bv1);
        }
        if (q < 2) {
            int sA = 2 * q, sB = 2 * q + 1;
            g0sh[sA][rowA] = d[0]; g0sh[sB][rowA] = d[1];
            g0sh[sA][rowB] = d[2]; g0sh[sB][rowB] = d[3];
        }
    }
    float xn = 0.f;
    if (tid < 64) xn = x[((size_t)(s0 + ps) * TW + min(1, TW - 1)) * INP + pk];
    __syncthreads();

    // ===================== encoder =====================
    for (int t = 0; t < Tenc; t++) {
        // ---- phase A: combine + activation STS + x rotate ----
        if (tid < 64) {
            uf0[ps][pk] = e4m3b(xn);
            int tt = (t + 2 < TW) ? t + 2 : TW - 1;
            xn = x[((size_t)(s0 + ps) * TW + tt) * INP + pk];
        }
        if (lay == 0) {
            if (t < myLe) {
                float fi = sigf(g0sh[cs][cj]);
                float ff = sigf(g0sh[cs][64 + cj]);
                float fg = tanha(g0sh[cs][128 + cj]);
                float fo = sigf(g0sh[cs][192 + cj]);
                cst = ff * cst + fi * fg;
                uint8_t hb = e4m3b(fo * tanha(cst));
                uf0[cs][16 + cj] = hb;   // h0 for g0 GEMM
                uf1[cs][cj]      = hb;   // h0 for g1 GEMM
            }
        } else {
            if (t > 0 && (t - 1) < myLe) {
                float fi = sigf(g1sh[cs][cj]);
                float ff = sigf(g1sh[cs][64 + cj]);
                float fg = tanha(g1sh[cs][128 + cj]);
                float fo = sigf(g1sh[cs][192 + cj]);
                cst = ff * cst + fi * fg;
                float h = fo * tanha(cst);
                uf1[cs][64 + cj] = e4m3b(h);
                h1sh[cs][cj] = h;
            }
        }
        __syncthreads();

        // ---- phase B: g1(t) and g0(t+1) via fp8 tensor cores ----
        {
            float e[4] = {b1a, b1a, b1b, b1b};
            #pragma unroll
            for (int ks = 0; ks < 4; ks++) {
                uint32_t bv0 = *(const uint32_t*)&uf1[g][ks * 32 + 4 * q];
                uint32_t bv1 = *(const uint32_t*)&uf1[g][ks * 32 + 16 + 4 * q];
                mma8(e, f1[ks], bv0, bv1);
            }
            float d[4] = {b0a, b0a, b0b, b0b};
            #pragma unroll
            for (int ks = 0; ks < 3; ks++) {
                uint32_t bv0 = *(const uint32_t*)&uf0[g][ks * 32 + 4 * q];
                uint32_t bv1 = *(const uint32_t*)&uf0[g][ks * 32 + 16 + 4 * q];
                mma8(d, f0[ks], bv0, bv1);
            }
            if (q < 2) {
                int sA = 2 * q, sB = 2 * q + 1;
                g1sh[sA][rowA] = e[0]; g1sh[sB][rowA] = e[1];
                g1sh[sA][rowB] = e[2]; g1sh[sB][rowB] = e[3];
                g0sh[sA][rowA] = d[0]; g0sh[sB][rowA] = d[1];
                g0sh[sA][rowB] = d[2]; g0sh[sB][rowB] = d[3];
            }
        }
        __syncthreads();
    }

    // ---- encoder epilogue: combine1(Tenc-1) ----
    if (lay == 1 && (Tenc - 1) < myLe) {
        float fi = sigf(g1sh[cs][cj]);
        float ff = sigf(g1sh[cs][64 + cj]);
        float fg = tanha(g1sh[cs][128 + cj]);
        float fo = sigf(g1sh[cs][192 + cj]);
        cst = ff * cst + fi * fg;
        float h = fo * tanha(cst);
        uf1[cs][64 + cj] = e4m3b(h);
        h1sh[cs][cj] = h;
    }
    __syncthreads();

    // ===================== element = h1 @ Wd.T + bd =====================
    if (tid < 32) {
        float a0 = bdsh[dk], a1 = 0.f, a2 = 0.f, a3 = 0.f;
        #pragma unroll
        for (int j = 0; j < HID; j += 4) {
            a0 = fmaf(wdsh[dk * 65 + j    ], h1sh[ds][j    ], a0);
            a1 = fmaf(wdsh[dk * 65 + j + 1], h1sh[ds][j + 1], a1);
            a2 = fmaf(wdsh[dk * 65 + j + 2], h1sh[ds][j + 2], a2);
            a3 = fmaf(wdsh[dk * 65 + j + 3], h1sh[ds][j + 3], a3);
        }
        float e = (a0 + a1) + (a2 + a3);
        elem[ds][dk] = e;
        out[(size_t)(s0 + ds) * TCC * FD + dk] = e;
    }
    __syncthreads();

    // ---- decoder prologue: dec input = [elem | ctx(0)]; g0_dec(0) via mma ----
    if (tid < 64 && pk < 8) uf0[ps][pk] = e4m3b(elem[ps][pk]);
    if (tid < 32) uf0[ds][8 + dk] = e4m3b(ctx[((size_t)(s0 + ds) * TCC) * FD + dk]);
    __syncthreads();
    {
        float d[4] = {b0a, b0a, b0b, b0b};
        #pragma unroll
        for (int ks = 0; ks < 3; ks++) {
            uint32_t bv0 = *(const uint32_t*)&uf0[g][ks * 32 + 4 * q];
            uint32_t bv1 = *(const uint32_t*)&uf0[g][ks * 32 + 16 + 4 * q];
            mma8(d, f0[ks], bv0, bv1);
        }
        if (q < 2) {
            int sA = 2 * q, sB = 2 * q + 1;
            g0sh[sA][rowA] = d[0]; g0sh[sB][rowA] = d[1];
            g0sh[sA][rowB] = d[2]; g0sh[sB][rowB] = d[3];
        }
    }
    float cn = 0.f;
    if (tid < 32) cn = ctx[((size_t)(s0 + ds) * TCC + min(1, TCC - 1)) * FD + dk];
    __syncthreads();

    // ===================== decoder =====================
    for (int t = 0; t < Tdec; t++) {
        // ---- phase A: combine + ctx rotate ----
        if (tid < 32) {
            uf0[ds][8 + dk] = e4m3b(cn);
            int tt = (t + 2 < TCC) ? t + 2 : TCC - 1;
            cn = ctx[((size_t)(s0 + ds) * TCC + tt) * FD + dk];
        }
        if (lay == 0) {
            if (t < myLd) {
                float fi = sigf(g0sh[cs][cj]);
                float ff = sigf(g0sh[cs][64 + cj]);
                float fg = tanha(g0sh[cs][128 + cj]);
                float fo = sigf(g0sh[cs][192 + cj]);
                cst = ff * cst + fi * fg;
                uint8_t hb = e4m3b(fo * tanha(cst));
                uf0[cs][16 + cj] = hb;
                uf1[cs][cj]      = hb;
            }
        } else {
            if (t > 0 && (t - 1) < myLd) {
                float fi = sigf(g1sh[cs][cj]);
                float ff = sigf(g1sh[cs][64 + cj]);
                float fg = tanha(g1sh[cs][128 + cj]);
                float fo = sigf(g1sh[cs][192 + cj]);
                cst = ff * cst + fi * fg;
                float h = fo * tanha(cst);
                uf1[cs][64 + cj] = e4m3b(h);
                h1sh[cs][cj] = h;
            }
        }
        __syncthreads();

        // ---- phase B: deferred projection (row t) + GEMMs ----
        if (tid < 32 && t > 0 && (t - 1) < ldec[ds]) {
            float a0 = bdsh[dk], a1 = 0.f, a2 = 0.f, a3 = 0.f;
            #pragma unroll
            for (int j = 0; j < HID; j += 4) {
                a0 = fmaf(wdsh[dk * 65 + j    ], h1sh[ds][j    ], a0);
                a1 = fmaf(wdsh[dk * 65 + j + 1], h1sh[ds][j + 1], a1);
                a2 = fmaf(wdsh[dk * 65 + j + 2], h1sh[ds][j + 2], a2);
                a3 = fmaf(wdsh[dk * 65 + j + 3], h1sh[ds][j + 3], a3);
            }
            out[((size_t)(s0 + ds) * TCC + t) * FD + dk] = (a0 + a1) + (a2 + a3);
        }
        {
            float e[4] = {b1a, b1a, b1b, b1b};
            #pragma unroll
            for (int ks = 0; ks < 4; ks++) {
                uint32_t bv0 = *(const uint32_t*)&uf1[g][ks * 32 + 4 * q];
                uint32_t bv1 = *(const uint32_t*)&uf1[g][ks * 32 + 16 + 4 * q];
                mma8(e, f1[ks], bv0, bv1);
            }
            float d[4] = {b0a, b0a, b0b, b0b};
            #pragma unroll
            for (int ks = 0; ks < 3; ks++) {
                uint32_t bv0 = *(const uint32_t*)&uf0[g][ks * 32 + 4 * q];
                uint32_t bv1 = *(const uint32_t*)&uf0[g][ks * 32 + 16 + 4 * q];
                mma8(d, f0[ks], bv0, bv1);
            }
            if (q < 2) {
                int sA = 2 * q, sB = 2 * q + 1;
                g1sh[sA][rowA] = e[0]; g1sh[sB][rowA] = e[1];
                g1sh[sA][rowB] = e[2]; g1sh[sB][rowB] = e[3];
                g0sh[sA][rowA] = d[0]; g0sh[sB][rowA] = d[1];
                g0sh[sA][rowB] = d[2]; g0sh[sB][rowB] = d[3];
            }
        }
        __syncthreads();
    }

    // ---- decoder epilogue: combine1(Tdec-1), then final projection ----
    if (lay == 1 && (Tdec - 1) < myLd) {
        float fi = sigf(g1sh[cs][cj]);
        float ff = sigf(g1sh[cs][64 + cj]);
        float fg = tanha(g1sh[cs][128 + cj]);
        float fo = sigf(g1sh[cs][192 + cj]);
        cst = ff * cst + fi * fg;
        h1sh[cs][cj] = fo * tanha(cst);
    }
    __syncthreads();
    if (tid < 32 && (Tdec - 1) < ldec[ds]) {
        float a0 = bdsh[dk], a1 = 0.f, a2 = 0.f, a3 = 0.f;
        #pragma unroll
        for (int j = 0; j < HID; j += 4) {
            a0 = fmaf(wdsh[dk * 65 + j    ], h1sh[ds][j    ], a0);
            a1 = fmaf(wdsh[dk * 65 + j + 1], h1sh[ds][j + 1], a1);
            a2 = fmaf(wdsh[dk * 65 + j + 2], h1sh[ds][j + 2], a2);
            a3 = fmaf(wdsh[dk * 65 + j + 3], h1sh[ds][j + 3], a3);
        }
        out[((size_t)(s0 + ds) * TCC + Tdec) * FD + dk] = (a0 + a1) + (a2 + a3);
    }
}

extern "C" void kernel_launch(void* const* d_in, const int* in_sizes, int n_in,
                              void* d_out, int out_size) {
    (void)in_sizes; (void)n_in; (void)out_size;
    lstm_ar_kernel<<<BB / SPB, NT>>>(
        (const float*)d_in[0],  (const int*)d_in[1],
        (const float*)d_in[2],  (const int*)d_in[3],
        (const float*)d_in[4],  (const float*)d_in[5],
        (const float*)d_in[6],  (const float*)d_in[7],
        (const float*)d_in[8],  (const float*)d_in[9],
        (const float*)d_in[10], (const float*)d_in[11],
        (const float*)d_in[12], (const float*)d_in[13],
        (float*)d_out);
}

// round 14
// speedup vs baseline: 1.3336x; 1.3336x over previous
#include <cuda_runtime.h>
#include <cuda_fp16.h>
#include <stdint.h>

#define BB   512
#define TW   512
#define TCC  512
#define INP  16
#define HID  64
#define FD   8
#define SPB  4
#define NT   512
#define HPAD 68
#define GPAD 260
#define U0S  88    // uf0 stride in halfs (K=80 + pad)
#define U1S  136   // uf1 stride in halfs (K=128 + pad)

#define BAR() asm volatile("bar.sync 0;" ::: "memory")

__device__ __forceinline__ float tanha(float x) {
    float r; asm("tanh.approx.f32 %0, %1;" : "=f"(r) : "f"(x)); return r;
}
__device__ __forceinline__ float sigf(float x) {
    return fmaf(tanha(0.5f * x), 0.5f, 0.5f);
}
__device__ __forceinline__ uint32_t h2(float a, float b) {
    __half2 h = __floats2half2_rn(a, b);
    return *reinterpret_cast<uint32_t*>(&h);
}
__device__ __forceinline__ void mma16816(
    float* d, const uint32_t* a, uint32_t b0, uint32_t b1)
{
    asm("mma.sync.aligned.m16n8k16.row.col.f32.f16.f16.f32 "
        "{%0,%1,%2,%3},{%4,%5,%6,%7},{%8,%9},{%0,%1,%2,%3};"
        : "+f"(d[0]), "+f"(d[1]), "+f"(d[2]), "+f"(d[3])
        : "r"(a[0]), "r"(a[1]), "r"(a[2]), "r"(a[3]), "r"(b0), "r"(b1));
}

__global__ __launch_bounds__(NT, 1) void lstm_ar_kernel(
    const float* __restrict__ x,     const int* __restrict__ lenx_g,
    const float* __restrict__ ctx,   const int* __restrict__ lctx_g,
    const float* __restrict__ Wih0,  const float* __restrict__ Whh0,
    const float* __restrict__ bih0,  const float* __restrict__ bhh0,
    const float* __restrict__ Wih1,  const float* __restrict__ Whh1,
    const float* __restrict__ bih1,  const float* __restrict__ bhh1,
    const float* __restrict__ Wd,    const float* __restrict__ bd,
    float* __restrict__ out)
{
    __shared__ __align__(16) __half uf0[8][U0S];   // [x(16)|h0(64)] per sample
    __shared__ __align__(16) __half uf1[8][U1S];   // [h0|h1] per sample
    __shared__ __align__(16) float g0sh[SPB][GPAD];
    __shared__ __align__(16) float g1sh[SPB][GPAD];
    __shared__ __align__(16) float h1sh[SPB][HPAD];
    __shared__ float wdsh[FD * 65];
    __shared__ float bdsh[FD];
    __shared__ float elem[SPB][FD];
    __shared__ int   lens[SPB];
    __shared__ int   ldec[SPB];

    const int tid = threadIdx.x;
    const int s0  = blockIdx.x * SPB;

    // ---- fill invalid output rows with -999 ----
    {
        const float4 m = make_float4(-999.f, -999.f, -999.f, -999.f);
        #pragma unroll
        for (int s = 0; s < SPB; s++) {
            int lc = lctx_g[s0 + s];
            float4* po = (float4*)(out + (size_t)(s0 + s) * TCC * FD);
            for (int i = lc * 2 + tid; i < (TCC * FD) / 4; i += NT) po[i] = m;
        }
    }
    // ---- zero B buffers (samples 4..7 + h parts stay zero initially) ----
    {
        __half z = __float2half(0.f);
        __half* p0 = &uf0[0][0];
        for (int i = tid; i < 8 * U0S; i += NT) p0[i] = z;
        __half* p1 = &uf1[0][0];
        for (int i = tid; i < 8 * U1S; i += NT) p1[i] = z;
    }
    if (tid < SPB) { lens[tid] = lenx_g[s0 + tid]; ldec[tid] = lctx_g[s0 + tid] - 1; }
    for (int i = tid; i < FD * HID; i += NT) wdsh[(i >> 6) * 65 + (i & 63)] = Wd[i];
    if (tid < FD) bdsh[tid] = bd[tid];
    __syncthreads();

    const int w = tid >> 5, lane = tid & 31;
    const int g = lane >> 2, q = lane & 3;
    const int c0 = 2 * q;
    const int Tenc = max(max(lens[0], lens[1]), max(lens[2], lens[3]));
    const int Tdec = max(max(ldec[0], ldec[1]), max(ldec[2], ldec[3]));

    if (w < 8) {
        // ================= LAYER-0 ENGINE (warps 0-7) =================
        const int rA0 = 32 * w + g,      rB0 = rA0 + 8;
        const int rA1 = 32 * w + 16 + g, rB1 = rA1 + 8;
        uint32_t f0[2][5][4];
        float b0A[2], b0B[2];
        #pragma unroll
        for (int j = 0; j < 2; j++) {
            int rA = j ? rA1 : rA0, rB = j ? rB1 : rB0;
            f0[j][0][0] = h2(Wih0[rA * INP + c0],     Wih0[rA * INP + c0 + 1]);
            f0[j][0][1] = h2(Wih0[rB * INP + c0],     Wih0[rB * INP + c0 + 1]);
            f0[j][0][2] = h2(Wih0[rA * INP + c0 + 8], Wih0[rA * INP + c0 + 9]);
            f0[j][0][3] = h2(Wih0[rB * INP + c0 + 8], Wih0[rB * INP + c0 + 9]);
            #pragma unroll
            for (int kt = 1; kt < 5; kt++) {
                int kb = (kt - 1) * 16;
                f0[j][kt][0] = h2(Whh0[rA * HID + kb + c0],     Whh0[rA * HID + kb + c0 + 1]);
                f0[j][kt][1] = h2(Whh0[rB * HID + kb + c0],     Whh0[rB * HID + kb + c0 + 1]);
                f0[j][kt][2] = h2(Whh0[rA * HID + kb + c0 + 8], Whh0[rA * HID + kb + c0 + 9]);
                f0[j][kt][3] = h2(Whh0[rB * HID + kb + c0 + 8], Whh0[rB * HID + kb + c0 + 9]);
            }
            b0A[j] = bih0[rA] + bhh0[rA]; b0B[j] = bih0[rB] + bhh0[rB];
        }
        const int cs = tid >> 6, cj = tid & 63;
        const int myLe = lens[cs], myLd = ldec[cs];
        const int ps = tid >> 4, pk = tid & 15;  // tid < 64
        const int ds = tid >> 3, dk = tid & 7;   // tid < 32
        float cst = 0.f;

        auto gemm0 = [&]() {
            float dA0[4] = {b0A[0], b0A[0], b0B[0], b0B[0]};
            float dA1[4] = {b0A[1], b0A[1], b0B[1], b0B[1]};
            float dB0[4] = {0.f, 0.f, 0.f, 0.f};
            float dB1[4] = {0.f, 0.f, 0.f, 0.f};
            #pragma unroll
            for (int kt = 0; kt < 3; kt++) {
                uint32_t bv0 = *(const uint32_t*)&uf0[g][kt * 16 + c0];
                uint32_t bv1 = *(const uint32_t*)&uf0[g][kt * 16 + c0 + 8];
                mma16816(dA0, f0[0][kt], bv0, bv1);
                mma16816(dA1, f0[1][kt], bv0, bv1);
            }
            #pragma unroll
            for (int kt = 3; kt < 5; kt++) {
                uint32_t bv0 = *(const uint32_t*)&uf0[g][kt * 16 + c0];
                uint32_t bv1 = *(const uint32_t*)&uf0[g][kt * 16 + c0 + 8];
                mma16816(dB0, f0[0][kt], bv0, bv1);
                mma16816(dB1, f0[1][kt], bv0, bv1);
            }
            if (q < 2) {
                int sA = 2 * q, sB = 2 * q + 1;
                g0sh[sA][rA0] = dA0[0] + dB0[0]; g0sh[sB][rA0] = dA0[1] + dB0[1];
                g0sh[sA][rB0] = dA0[2] + dB0[2]; g0sh[sB][rB0] = dA0[3] + dB0[3];
                g0sh[sA][rA1] = dA1[0] + dB1[0]; g0sh[sB][rA1] = dA1[1] + dB1[1];
                g0sh[sA][rB1] = dA1[2] + dB1[2]; g0sh[sB][rB1] = dA1[3] + dB1[3];
            }
        };
        auto comb0 = [&]() {
            float fi = sigf(g0sh[cs][cj]);
            float ff = sigf(g0sh[cs][64 + cj]);
            float fg = tanha(g0sh[cs][128 + cj]);
            float fo = sigf(g0sh[cs][192 + cj]);
            cst = ff * cst + fi * fg;
            __half hf = __float2half(fo * tanha(cst));
            uf0[cs][16 + cj] = hf;
            uf1[cs][cj]      = hf;
        };
        auto proj = [&](int row) {   // tid < 32 only
            float a0 = bdsh[dk], a1 = 0.f, a2 = 0.f, a3 = 0.f;
            #pragma unroll
            for (int j = 0; j < HID; j += 4) {
                a0 = fmaf(wdsh[dk * 65 + j    ], h1sh[ds][j    ], a0);
                a1 = fmaf(wdsh[dk * 65 + j + 1], h1sh[ds][j + 1], a1);
                a2 = fmaf(wdsh[dk * 65 + j + 2], h1sh[ds][j + 2], a2);
                a3 = fmaf(wdsh[dk * 65 + j + 3], h1sh[ds][j + 3], a3);
            }
            out[((size_t)(s0 + ds) * TCC + row) * FD + dk] = (a0 + a1) + (a2 + a3);
        };

        // ---- encoder prologue ----
        if (tid < 64) uf0[ps][pk] = __float2half(x[((size_t)(s0 + ps) * TW) * INP + pk]);
        BAR();                                   // bar 1
        gemm0();                                 // g0(0), h0 = 0
        float xn = 0.f;
        if (tid < 64) xn = x[((size_t)(s0 + ps) * TW + min(1, TW - 1)) * INP + pk];
        BAR();                                   // bar 2
        // ---- encoder ----
        for (int t = 0; t < Tenc; t++) {
            if (tid < 64) {
                uf0[ps][pk] = __float2half(xn);
                int tt = (t + 2 < TW) ? t + 2 : TW - 1;
                xn = x[((size_t)(s0 + ps) * TW + tt) * INP + pk];
            }
            if (t < myLe) comb0();
            BAR();                               // loop bar a
            gemm0();                             // g0(t+1)
            BAR();                               // loop bar b
        }
        BAR();                                   // bar: L1 combine1(Tenc-1)
        // ---- element = h1 @ Wd.T + bd ----
        if (tid < 32) {
            float a0 = bdsh[dk], a1 = 0.f, a2 = 0.f, a3 = 0.f;
            #pragma unroll
            for (int j = 0; j < HID; j += 4) {
                a0 = fmaf(wdsh[dk * 65 + j    ], h1sh[ds][j    ], a0);
                a1 = fmaf(wdsh[dk * 65 + j + 1], h1sh[ds][j + 1], a1);
                a2 = fmaf(wdsh[dk * 65 + j + 2], h1sh[ds][j + 2], a2);
                a3 = fmaf(wdsh[dk * 65 + j + 3], h1sh[ds][j + 3], a3);
            }
            float e = (a0 + a1) + (a2 + a3);
            elem[ds][dk] = e;
            out[(size_t)(s0 + ds) * TCC * FD + dk] = e;   // row 0
        }
        BAR();                                   // bar: elem ready
        // ---- decoder prologue ----
        if (tid < 64 && pk < 8) uf0[ps][pk] = __float2half(elem[ps][pk]);
        if (tid < 32) uf0[ds][8 + dk] = __float2half(ctx[((size_t)(s0 + ds) * TCC) * FD + dk]);
        BAR();                                   // bar: dec input ready
        gemm0();                                 // g0_dec(0)
        float cn = 0.f;
        if (tid < 32) cn = ctx[((size_t)(s0 + ds) * TCC + min(1, TCC - 1)) * FD + dk];
        BAR();                                   // bar
        // ---- decoder ----
        for (int t = 0; t < Tdec; t++) {
            if (tid < 32) {
                uf0[ds][8 + dk] = __float2half(cn);
                int tt = (t + 2 < TCC) ? t + 2 : TCC - 1;
                cn = ctx[((size_t)(s0 + ds) * TCC + tt) * FD + dk];
            }
            if (t < myLd) comb0();
            BAR();                               // loop bar a
            if (tid < 32 && t > 0 && (t - 1) < ldec[ds]) proj(t);
            gemm0();                             // g0(t+1)
            BAR();                               // loop bar b
        }
        BAR();                                   // bar: L1 combine1(Tdec-1)
        if (tid < 32 && (Tdec - 1) < ldec[ds]) proj(Tdec);
    } else {
        // ================= LAYER-1 ENGINE (warps 8-15) =================
        const int wj  = w - 8;
        const int rA0 = 32 * wj + g,      rB0 = rA0 + 8;
        const int rA1 = 32 * wj + 16 + g, rB1 = rA1 + 8;
        uint32_t f1[2][8][4];
        float b1A[2], b1B[2];
        #pragma unroll
        for (int j = 0; j < 2; j++) {
            int rA = j ? rA1 : rA0, rB = j ? rB1 : rB0;
            #pragma unroll
            for (int kt = 0; kt < 4; kt++) {
                int kb = kt * 16;
                f1[j][kt][0] = h2(Wih1[rA * HID + kb + c0],     Wih1[rA * HID + kb + c0 + 1]);
                f1[j][kt][1] = h2(Wih1[rB * HID + kb + c0],     Wih1[rB * HID + kb + c0 + 1]);
                f1[j][kt][2] = h2(Wih1[rA * HID + kb + c0 + 8], Wih1[rA * HID + kb + c0 + 9]);
                f1[j][kt][3] = h2(Wih1[rB * HID + kb + c0 + 8], Wih1[rB * HID + kb + c0 + 9]);
            }
            #pragma unroll
            for (int kt = 4; kt < 8; kt++) {
                int kb = (kt - 4) * 16;
                f1[j][kt][0] = h2(Whh1[rA * HID + kb + c0],     Whh1[rA * HID + kb + c0 + 1]);
                f1[j][kt][1] = h2(Whh1[rB * HID + kb + c0],     Whh1[rB * HID + kb + c0 + 1]);
                f1[j][kt][2] = h2(Whh1[rA * HID + kb + c0 + 8], Whh1[rA * HID + kb + c0 + 9]);
                f1[j][kt][3] = h2(Whh1[rB * HID + kb + c0 + 8], Whh1[rB * HID + kb + c0 + 9]);
            }
            b1A[j] = bih1[rA] + bhh1[rA]; b1B[j] = bih1[rB] + bhh1[rB];
        }
        const int cu = tid - 256;
        const int cs = cu >> 6, cj = cu & 63;
        const int myLe = lens[cs], myLd = ldec[cs];
        float cst = 0.f;

        auto gemm1 = [&]() {
            float eA0[4] = {b1A[0], b1A[0], b1B[0], b1B[0]};
            float eA1[4] = {b1A[1], b1A[1], b1B[1], b1B[1]};
            float eB0[4] = {0.f, 0.f, 0.f, 0.f};
            float eB1[4] = {0.f, 0.f, 0.f, 0.f};
            #pragma unroll
            for (int kt = 0; kt < 4; kt++) {
                uint32_t bv0 = *(const uint32_t*)&uf1[g][kt * 16 + c0];
                uint32_t bv1 = *(const uint32_t*)&uf1[g][kt * 16 + c0 + 8];
                mma16816(eA0, f1[0][kt], bv0, bv1);
                mma16816(eA1, f1[1][kt], bv0, bv1);
            }
            #pragma unroll
            for (int kt = 4; kt < 8; kt++) {
                uint32_t bv0 = *(const uint32_t*)&uf1[g][kt * 16 + c0];
                uint32_t bv1 = *(const uint32_t*)&uf1[g][kt * 16 + c0 + 8];
                mma16816(eB0, f1[0][kt], bv0, bv1);
                mma16816(eB1, f1[1][kt], bv0, bv1);
            }
            if (q < 2) {
                int sA = 2 * q, sB = 2 * q + 1;
                g1sh[sA][rA0] = eA0[0] + eB0[0]; g1sh[sB][rA0] = eA0[1] + eB0[1];
                g1sh[sA][rB0] = eA0[2] + eB0[2]; g1sh[sB][rB0] = eA0[3] + eB0[3];
                g1sh[sA][rA1] = eA1[0] + eB1[0]; g1sh[sB][rA1] = eA1[1] + eB1[1];
                g1sh[sA][rB1] = eA1[2] + eB1[2]; g1sh[sB][rB1] = eA1[3] + eB1[3];
            }
        };
        auto comb1 = [&]() {
            float fi = sigf(g1sh[cs][cj]);
            float ff = sigf(g1sh[cs][64 + cj]);
            float fg = tanha(g1sh[cs][128 + cj]);
            float fo = sigf(g1sh[cs][192 + cj]);
            cst = ff * cst + fi * fg;
            float h = fo * tanha(cst);
            uf1[cs][64 + cj] = __float2half(h);
            h1sh[cs][cj] = h;
        };

        // ---- encoder prologue (mirror bars) ----
        BAR();                                   // bar 1
        BAR();                                   // bar 2
        // ---- encoder ----
        for (int t = 0; t < Tenc; t++) {
            if (t > 0 && (t - 1) < myLe) comb1();
            BAR();                               // loop bar a
            gemm1();                             // g1(t)
            BAR();                               // loop bar b
        }
        if ((Tenc - 1) < myLe) comb1();
        BAR();                                   // bar: h1 final ready
        BAR();                                   // bar: elem
        BAR();                                   // bar: dec input
        BAR();                                   // bar: g0_dec(0)
        // ---- decoder ----
        for (int t = 0; t < Tdec; t++) {
            if (t > 0 && (t - 1) < myLd) comb1();
            BAR();                               // loop bar a
            gemm1();                             // g1(t)
            BAR();                               // loop bar b
        }
        if ((Tdec - 1) < myLd) comb1();
        BAR();                                   // bar: h1(Tdec-1) ready
    }
}

extern "C" void kernel_launch(void* const* d_in, const int* in_sizes, int n_in,
                              void* d_out, int out_size) {
    (void)in_sizes; (void)n_in; (void)out_size;
    lstm_ar_kernel<<<BB / SPB, NT>>>(
        (const float*)d_in[0],  (const int*)d_in[1],
        (const float*)d_in[2],  (const int*)d_in[3],
        (const float*)d_in[4],  (const float*)d_in[5],
        (const float*)d_in[6],  (const float*)d_in[7],
        (const float*)d_in[8],  (const float*)d_in[9],
        (const float*)d_in[10], (const float*)d_in[11],
        (const float*)d_in[12], (const float*)d_in[13],
        (float*)d_out);
}